// round 8
// baseline (speedup 1.0000x reference)
#include <cuda_runtime.h>
#include <cuda_bf16.h>
#include <math.h>
#include <cstdint>

#define BATCH 16384
__device__ __nv_bfloat16 g_latent_bf[BATCH * 224];
__device__ __nv_bfloat16 g_wfc_bf[392 * 224];
__device__ float g_h[BATCH * 392];

__device__ __forceinline__ uint32_t smem_u32(const void* p) {
    uint32_t a;
    asm("{ .reg .u64 t; cvta.to.shared.u64 t, %1; cvt.u32.u64 %0, t; }" : "=r"(a) : "l"(p));
    return a;
}
__device__ __forceinline__ void ldmatrix_x4(uint32_t& r0, uint32_t& r1, uint32_t& r2, uint32_t& r3,
                                            uint32_t addr) {
    asm volatile("ldmatrix.sync.aligned.m8n8.x4.shared.b16 {%0,%1,%2,%3}, [%4];"
                 : "=r"(r0), "=r"(r1), "=r"(r2), "=r"(r3) : "r"(addr));
}
__device__ __forceinline__ void mma_16816(float* d, const uint32_t* a, const uint32_t* b) {
    asm volatile(
        "mma.sync.aligned.m16n8k16.row.col.f32.bf16.bf16.f32 "
        "{%0,%1,%2,%3}, {%4,%5,%6,%7}, {%8,%9}, {%0,%1,%2,%3};"
        : "+f"(d[0]), "+f"(d[1]), "+f"(d[2]), "+f"(d[3])
        : "r"(a[0]), "r"(a[1]), "r"(a[2]), "r"(a[3]), "r"(b[0]), "r"(b[1]));
}

// ---------------------------------------------------------------------------
// Kernel 1: quadrant means -> 4-qubit sim -> latent (bf16) = relu(qf@w_lat^T+b)
// ---------------------------------------------------------------------------
__global__ void __launch_bounds__(256) k1_quad_latent(
    const float* __restrict__ x,
    const float* __restrict__ var_params,
    const float* __restrict__ w_lat,
    const float* __restrict__ b_lat)
{
    const int warp = threadIdx.x >> 5;
    const int lane = threadIdx.x & 31;
    const int b = blockIdx.x * 8 + warp;

    const float4* xb4 = (const float4*)(x + (size_t)b * 784);
    float q0 = 0.f, q1 = 0.f, q2 = 0.f, q3 = 0.f;
#pragma unroll
    for (int it = 0; it < 7; it++) {
        int f = lane + 32 * it;
        if (f < 196) {
            float4 v = xb4[f];
            int row = f / 7;
            int cg  = f - row * 7;
            float s4  = (v.x + v.y) + (v.z + v.w);
            float lft = (cg < 3) ? s4 : ((cg == 3) ? (v.x + v.y) : 0.f);
            float rgt = s4 - lft;
            if (row < 14) { q0 += lft; q1 += rgt; }
            else          { q2 += lft; q3 += rgt; }
        }
    }
#pragma unroll
    for (int off = 16; off; off >>= 1) {
        q0 += __shfl_xor_sync(0xFFFFFFFFu, q0, off);
        q1 += __shfl_xor_sync(0xFFFFFFFFu, q1, off);
        q2 += __shfl_xor_sync(0xFFFFFFFFu, q2, off);
        q3 += __shfl_xor_sync(0xFFFFFFFFu, q3, off);
    }
    const float inv196 = 1.0f / 196.0f;
    float ang[4] = { q0 * inv196, q1 * inv196, q2 * inv196, q3 * inv196 };

    float cc[4], ss[4];
#pragma unroll
    for (int q = 0; q < 4; q++) {
        float th = 0.5f * ang[q];
        cc[q] = __cosf(th);
        ss[q] = __sinf(th);
    }
    float re[16], im[16];
#pragma unroll
    for (int i = 0; i < 16; i++) {
        re[i] = ((i & 8) ? ss[0] : cc[0]) * ((i & 4) ? ss[1] : cc[1]) *
                ((i & 2) ? ss[2] : cc[2]) * ((i & 1) ? ss[3] : cc[3]);
        im[i] = 0.f;
    }
#pragma unroll
    for (int q = 0; q < 4; q++) {
        float ph = 0.5f * var_params[q];
        float hc = __cosf(ph), hs = __sinf(ph);
        const int mq = 8 >> q;
        const int mt = 8 >> ((q + 1) & 3);
#pragma unroll
        for (int i = 0; i < 16; i++) {
            float sg = (i & mq) ? hs : -hs;
            float nr = re[i] * hc - im[i] * sg;
            float ni = re[i] * sg + im[i] * hc;
            re[i] = nr; im[i] = ni;
        }
#pragma unroll
        for (int i = 0; i < 16; i++) {
            if ((i & mq) && !(i & mt)) {
                int j2 = i | mt;
                float tr = re[i]; re[i] = re[j2]; re[j2] = tr;
                float ti = im[i]; im[i] = im[j2]; im[j2] = ti;
            }
        }
    }
    float z0 = 0.f, z1 = 0.f, z2 = 0.f, z3 = 0.f;
#pragma unroll
    for (int i = 0; i < 16; i++) {
        float p = re[i] * re[i] + im[i] * im[i];
        z0 += (i & 8) ? -p : p;
        z1 += (i & 4) ? -p : p;
        z2 += (i & 2) ? -p : p;
        z3 += (i & 1) ? -p : p;
    }
    for (int r = lane; r < 224; r += 32) {
        float4 w = *(const float4*)(w_lat + (size_t)r * 4);
        float a = b_lat[r];
        a = fmaf(w.x, z0, a);
        a = fmaf(w.y, z1, a);
        a = fmaf(w.z, z2, a);
        a = fmaf(w.w, z3, a);
        g_latent_bf[(size_t)b * 224 + r] = __float2bfloat16(fmaxf(a, 0.f));
    }
}

// ---------------------------------------------------------------------------
// Kernel 2a: convert w_fc (392x224 fp32) -> bf16
// ---------------------------------------------------------------------------
__global__ void __launch_bounds__(256) k2a_convert(const float* __restrict__ w_fc) {
    int i = blockIdx.x * 256 + threadIdx.x;
    if (i < 392 * 224 / 4) {
        float4 v = *(const float4*)(w_fc + i * 4);
        __nv_bfloat16* d = g_wfc_bf + i * 4;
        d[0] = __float2bfloat16(v.x);
        d[1] = __float2bfloat16(v.y);
        d[2] = __float2bfloat16(v.z);
        d[3] = __float2bfloat16(v.w);
    }
}

// ---------------------------------------------------------------------------
// Kernel 2: HMMA bf16 GEMM: h = relu(latent @ w_fc^T + b_fc)
// ---------------------------------------------------------------------------
#define ASTR 232
#define K2_SMEM_BYTES ((128 * ASTR + 64 * ASTR) * 2)

__global__ void __launch_bounds__(256, 2) k2_gemm_mma(
    const float* __restrict__ b_fc)
{
    extern __shared__ __align__(16) __nv_bfloat16 sm[];
    __nv_bfloat16* sa = sm;               // [128][ASTR]
    __nv_bfloat16* sb = sm + 128 * ASTR;  // [64][ASTR]

    const int tid = threadIdx.x;
    const int wid = tid >> 5;
    const int lane = tid & 31;
    const int n0 = blockIdx.x * 64;
    const int m0 = blockIdx.y * 128;
    const int mw = (wid & 3) * 32;
    const int nw = (wid >> 2) * 32;

    for (int t = tid; t < 128 * 28; t += 256) {
        int r = t / 28, c = t - (t / 28) * 28;
        uint4 v = *(const uint4*)(g_latent_bf + (size_t)(m0 + r) * 224 + c * 8);
        *(uint4*)(sa + r * ASTR + c * 8) = v;
    }
    for (int t = tid; t < 64 * 28; t += 256) {
        int r = t / 28, c = t - (t / 28) * 28;
        int gn = n0 + r;
        uint4 v = make_uint4(0u, 0u, 0u, 0u);
        if (gn < 392) v = *(const uint4*)(g_wfc_bf + (size_t)gn * 224 + c * 8);
        *(uint4*)(sb + r * ASTR + c * 8) = v;
    }
    __syncthreads();

    float d[2][4][4];
#pragma unroll
    for (int mt = 0; mt < 2; mt++)
#pragma unroll
        for (int nt = 0; nt < 4; nt++)
#pragma unroll
            for (int e = 0; e < 4; e++) d[mt][nt][e] = 0.f;

    const uint32_t sa_base = smem_u32(sa);
    const uint32_t sb_base = smem_u32(sb);
    const int a_row = mw + (lane & 15);
    const int a_coff = (lane >> 4) * 8;
    const int b_row = nw + (lane & 7) + ((lane >> 4) & 1) * 8;
    const int b_coff = ((lane >> 3) & 1) * 8;

#pragma unroll
    for (int ks = 0; ks < 14; ks++) {
        const int k0 = ks * 16;
        uint32_t a0[4], a1[4];
        ldmatrix_x4(a0[0], a0[1], a0[2], a0[3],
                    sa_base + (uint32_t)((a_row) * ASTR + k0 + a_coff) * 2);
        ldmatrix_x4(a1[0], a1[1], a1[2], a1[3],
                    sa_base + (uint32_t)((a_row + 16) * ASTR + k0 + a_coff) * 2);
        uint32_t b01[4], b23[4];
        ldmatrix_x4(b01[0], b01[1], b01[2], b01[3],
                    sb_base + (uint32_t)((b_row) * ASTR + k0 + b_coff) * 2);
        ldmatrix_x4(b23[0], b23[1], b23[2], b23[3],
                    sb_base + (uint32_t)((b_row + 16) * ASTR + k0 + b_coff) * 2);
        mma_16816(d[0][0], a0, b01 + 0);
        mma_16816(d[0][1], a0, b01 + 2);
        mma_16816(d[0][2], a0, b23 + 0);
        mma_16816(d[0][3], a0, b23 + 2);
        mma_16816(d[1][0], a1, b01 + 0);
        mma_16816(d[1][1], a1, b01 + 2);
        mma_16816(d[1][2], a1, b23 + 0);
        mma_16816(d[1][3], a1, b23 + 2);
    }

    const int qrow = lane >> 2;
    const int qcol = (lane & 3) * 2;
#pragma unroll
    for (int nt = 0; nt < 4; nt++) {
        int gn = n0 + nw + nt * 8 + qcol;
        if (gn < 392) {
            float2 bv = *(const float2*)(b_fc + gn);
#pragma unroll
            for (int mt = 0; mt < 2; mt++) {
                int m = m0 + mw + mt * 16 + qrow;
                float2 o0, o1;
                o0.x = fmaxf(d[mt][nt][0] + bv.x, 0.f);
                o0.y = fmaxf(d[mt][nt][1] + bv.y, 0.f);
                o1.x = fmaxf(d[mt][nt][2] + bv.x, 0.f);
                o1.y = fmaxf(d[mt][nt][3] + bv.y, 0.f);
                *(float2*)(g_h + (size_t)m * 392 + gn) = o0;
                *(float2*)(g_h + (size_t)(m + 8) * 392 + gn) = o1;
            }
        }
    }
}

// ---------------------------------------------------------------------------
// Kernel 3: fused deconv1+relu+deconv2+sigmoid, parity-class mapping.
// Block = 256 threads / 4 samples. Thread's parity class pc = tid>>6 fixes
// (I&1, J&1) -> its 32 w_d1 weights live in REGISTERS (loaded once).
// Per item: 8 stride-1 LDS (h channels) + 4 LDS.128 (w2 rows) + 48 FMA.
// ---------------------------------------------------------------------------
__global__ void __launch_bounds__(256) k3_deconv(
    const float* __restrict__ w_d1, const float* __restrict__ b_d1,
    const float* __restrict__ w_d2, const float* __restrict__ b_d2,
    float* __restrict__ out)
{
    __shared__ float shh[4 * 392];
    __shared__ float sw2r[16];     // [dk][o] layout
    __shared__ float sb1[4];
    __shared__ float sb2s;

    const int tid = threadIdx.x;
    const int b0 = blockIdx.x * 4;

    if (tid < 16) sw2r[tid] = w_d2[(tid & 3) * 4 + (tid >> 2)];  // sw2r[dk*4+o]
    else if (tid < 20) sb1[tid - 16] = b_d1[tid - 16];
    else if (tid == 20) sb2s = b_d2[0];

    // stage 4 samples of h: 1568 contiguous floats = 392 float4, coalesced
    {
        const float4* src = (const float4*)(g_h + (size_t)b0 * 392);
        float4* dst = (float4*)shh;
        dst[tid] = src[tid];
        if (tid < 136) dst[256 + tid] = src[256 + tid];
    }

    // per-thread parity class: 32 w_d1 weights -> registers
    const int pc = tid >> 6;       // (d1<<1)|k1
    const int u  = tid & 63;
    float w1[8][4];
#pragma unroll
    for (int c = 0; c < 8; c++)
#pragma unroll
        for (int o = 0; o < 4; o++)
            w1[c][o] = __ldg(w_d1 + c * 16 + o * 4 + pc);
    __syncthreads();

    const int Ioff = (pc >> 1);
    const int Joff = (pc & 1);

    for (int item = u; item < 196; item += 64) {
        const int s = item / 49;
        const int q = item - s * 49;
        const int i = q / 7;
        const int j = q - i * 7;

        const float* hp = shh + s * 392 + q;
        float y[4];
        {
            float a0 = sb1[0], a1 = sb1[1], a2 = sb1[2], a3 = sb1[3];
#pragma unroll
            for (int c = 0; c < 8; c++) {
                float hv = hp[c * 49];
                a0 = fmaf(hv, w1[c][0], a0);
                a1 = fmaf(hv, w1[c][1], a1);
                a2 = fmaf(hv, w1[c][2], a2);
                a3 = fmaf(hv, w1[c][3], a3);
            }
            y[0] = fmaxf(a0, 0.f); y[1] = fmaxf(a1, 0.f);
            y[2] = fmaxf(a2, 0.f); y[3] = fmaxf(a3, 0.f);
        }
        float v[4];
#pragma unroll
        for (int dk = 0; dk < 4; dk++) {
            float4 w2v = *(const float4*)(sw2r + dk * 4);
            float a = sb2s;
            a = fmaf(y[0], w2v.x, a);
            a = fmaf(y[1], w2v.y, a);
            a = fmaf(y[2], w2v.z, a);
            a = fmaf(y[3], w2v.w, a);
            v[dk] = __fdividef(1.0f, 1.0f + __expf(-a));
        }
        const int I = 2 * i + Ioff;
        const int J = 2 * j + Joff;
        float* ob = out + (size_t)(b0 + s) * 784 + (2 * I) * 28 + 2 * J;
        *(float2*)(ob)      = make_float2(v[0], v[1]);
        *(float2*)(ob + 28) = make_float2(v[2], v[3]);
    }
}

// ---------------------------------------------------------------------------
// Launch
// ---------------------------------------------------------------------------
extern "C" void kernel_launch(void* const* d_in, const int* in_sizes, int n_in,
                              void* d_out, int out_size)
{
    const float* x          = (const float*)d_in[0];
    const float* var_params = (const float*)d_in[1];
    const float* w_lat      = (const float*)d_in[2];
    const float* b_lat      = (const float*)d_in[3];
    const float* w_fc       = (const float*)d_in[4];
    const float* b_fc       = (const float*)d_in[5];
    const float* w_d1       = (const float*)d_in[6];
    const float* b_d1       = (const float*)d_in[7];
    const float* w_d2       = (const float*)d_in[8];
    const float* b_d2       = (const float*)d_in[9];
    float* out = (float*)d_out;

    cudaFuncSetAttribute(k2_gemm_mma, cudaFuncAttributeMaxDynamicSharedMemorySize,
                         K2_SMEM_BYTES);

    k1_quad_latent<<<BATCH / 8, 256>>>(x, var_params, w_lat, b_lat);
    k2a_convert<<<(392 * 224 / 4 + 255) / 256, 256>>>(w_fc);
    k2_gemm_mma<<<dim3(7, BATCH / 128), 256, K2_SMEM_BYTES>>>(b_fc);
    k3_deconv<<<BATCH / 4, 256>>>(w_d1, b_d1, w_d2, b_d2, out);
}

// round 10
// speedup vs baseline: 1.1504x; 1.1504x over previous
#include <cuda_runtime.h>
#include <cuda_bf16.h>
#include <math.h>
#include <cstdint>

#define BATCH 16384
__device__ __nv_bfloat16 g_latent_bf[BATCH * 224];
__device__ __nv_bfloat16 g_wfc_bf[392 * 224];
__device__ float g_h[BATCH * 392];

__device__ __forceinline__ uint32_t smem_u32(const void* p) {
    uint32_t a;
    asm("{ .reg .u64 t; cvta.to.shared.u64 t, %1; cvt.u32.u64 %0, t; }" : "=r"(a) : "l"(p));
    return a;
}
__device__ __forceinline__ void ldmatrix_x4(uint32_t& r0, uint32_t& r1, uint32_t& r2, uint32_t& r3,
                                            uint32_t addr) {
    asm volatile("ldmatrix.sync.aligned.m8n8.x4.shared.b16 {%0,%1,%2,%3}, [%4];"
                 : "=r"(r0), "=r"(r1), "=r"(r2), "=r"(r3) : "r"(addr));
}
__device__ __forceinline__ void mma_16816(float* d, const uint32_t* a, const uint32_t* b) {
    asm volatile(
        "mma.sync.aligned.m16n8k16.row.col.f32.bf16.bf16.f32 "
        "{%0,%1,%2,%3}, {%4,%5,%6,%7}, {%8,%9}, {%0,%1,%2,%3};"
        : "+f"(d[0]), "+f"(d[1]), "+f"(d[2]), "+f"(d[3])
        : "r"(a[0]), "r"(a[1]), "r"(a[2]), "r"(a[3]), "r"(b[0]), "r"(b[1]));
}

// ---------------------------------------------------------------------------
// Kernel 1: 32 samples per 256-thread block.
//  Phase 1: 8 threads/sample quadrant reduce (coalesced float4).
//  Phase 2: warp 0 only, lane = sample: 4-qubit sim (no 8x redundancy).
//  Phase 3: all threads: latent GEMV from smem, packed bf16x2 stores.
// ---------------------------------------------------------------------------
__global__ void __launch_bounds__(256) k1_quad_latent(
    const float* __restrict__ x,
    const float* __restrict__ var_params,
    const float* __restrict__ w_lat,
    const float* __restrict__ b_lat)
{
    __shared__ float sang[32][4];
    __shared__ float sz[32][4];
    __shared__ float4 swlat[224];
    __shared__ float sbl[224];

    const int tid = threadIdx.x;
    const int b0 = blockIdx.x * 32;
    const int s = tid >> 3;
    const int sub = tid & 7;

    // stage w_lat (224 float4) + b_lat
    if (tid < 224) {
        swlat[tid] = *(const float4*)(w_lat + tid * 4);
        sbl[tid] = b_lat[tid];
    }

    // ---- phase 1: quadrant sums, 8 threads per sample ----
    {
        const float4* xb4 = (const float4*)(x + (size_t)(b0 + s) * 784);
        float q0 = 0.f, q1 = 0.f, q2 = 0.f, q3 = 0.f;
#pragma unroll
        for (int it = 0; it < 25; it++) {
            int f = sub + 8 * it;
            if (f < 196) {
                float4 v = xb4[f];
                int row = f / 7;
                int cg  = f - row * 7;
                float s4  = (v.x + v.y) + (v.z + v.w);
                float lft = (cg < 3) ? s4 : ((cg == 3) ? (v.x + v.y) : 0.f);
                float rgt = s4 - lft;
                if (row < 14) { q0 += lft; q1 += rgt; }
                else          { q2 += lft; q3 += rgt; }
            }
        }
#pragma unroll
        for (int off = 4; off; off >>= 1) {
            q0 += __shfl_xor_sync(0xFFFFFFFFu, q0, off);
            q1 += __shfl_xor_sync(0xFFFFFFFFu, q1, off);
            q2 += __shfl_xor_sync(0xFFFFFFFFu, q2, off);
            q3 += __shfl_xor_sync(0xFFFFFFFFu, q3, off);
        }
        if (sub == 0) {
            const float inv196 = 1.0f / 196.0f;
            sang[s][0] = q0 * inv196;
            sang[s][1] = q1 * inv196;
            sang[s][2] = q2 * inv196;
            sang[s][3] = q3 * inv196;
        }
    }
    __syncthreads();

    // ---- phase 2: warp 0, lane = sample ----
    if (tid < 32) {
        float cc[4], ss[4];
#pragma unroll
        for (int q = 0; q < 4; q++) {
            float th = 0.5f * sang[tid][q];
            cc[q] = __cosf(th);
            ss[q] = __sinf(th);
        }
        float re[16], im[16];
#pragma unroll
        for (int i = 0; i < 16; i++) {
            re[i] = ((i & 8) ? ss[0] : cc[0]) * ((i & 4) ? ss[1] : cc[1]) *
                    ((i & 2) ? ss[2] : cc[2]) * ((i & 1) ? ss[3] : cc[3]);
            im[i] = 0.f;
        }
#pragma unroll
        for (int q = 0; q < 4; q++) {
            float ph = 0.5f * var_params[q];
            float hcv = __cosf(ph), hsv = __sinf(ph);
            const int mq = 8 >> q;
            const int mt = 8 >> ((q + 1) & 3);
#pragma unroll
            for (int i = 0; i < 16; i++) {
                float sg = (i & mq) ? hsv : -hsv;
                float nr = re[i] * hcv - im[i] * sg;
                float ni = re[i] * sg + im[i] * hcv;
                re[i] = nr; im[i] = ni;
            }
#pragma unroll
            for (int i = 0; i < 16; i++) {
                if ((i & mq) && !(i & mt)) {
                    int j2 = i | mt;
                    float tr = re[i]; re[i] = re[j2]; re[j2] = tr;
                    float ti = im[i]; im[i] = im[j2]; im[j2] = ti;
                }
            }
        }
        float z0 = 0.f, z1 = 0.f, z2 = 0.f, z3 = 0.f;
#pragma unroll
        for (int i = 0; i < 16; i++) {
            float p = re[i] * re[i] + im[i] * im[i];
            z0 += (i & 8) ? -p : p;
            z1 += (i & 4) ? -p : p;
            z2 += (i & 2) ? -p : p;
            z3 += (i & 1) ? -p : p;
        }
        sz[tid][0] = z0; sz[tid][1] = z1; sz[tid][2] = z2; sz[tid][3] = z3;
    }
    __syncthreads();

    // ---- phase 3: latent GEMV, 2 outputs (one bf16x2) per iteration ----
    __nv_bfloat162* lat2 = (__nv_bfloat162*)g_latent_bf;
    for (int idx = tid; idx < 32 * 112; idx += 256) {
        int ls = idx / 112;
        int rp = idx - ls * 112;
        int r = rp * 2;
        float4 zv = *(const float4*)sz[ls];
        float4 w0 = swlat[r];
        float4 w1 = swlat[r + 1];
        float a0 = sbl[r];
        a0 = fmaf(w0.x, zv.x, a0); a0 = fmaf(w0.y, zv.y, a0);
        a0 = fmaf(w0.z, zv.z, a0); a0 = fmaf(w0.w, zv.w, a0);
        float a1 = sbl[r + 1];
        a1 = fmaf(w1.x, zv.x, a1); a1 = fmaf(w1.y, zv.y, a1);
        a1 = fmaf(w1.z, zv.z, a1); a1 = fmaf(w1.w, zv.w, a1);
        __nv_bfloat162 o;
        o.x = __float2bfloat16(fmaxf(a0, 0.f));
        o.y = __float2bfloat16(fmaxf(a1, 0.f));
        lat2[(size_t)(b0 + ls) * 112 + rp] = o;
    }
}

// ---------------------------------------------------------------------------
// Kernel 2a: convert w_fc (392x224 fp32) -> bf16
// ---------------------------------------------------------------------------
__global__ void __launch_bounds__(256) k2a_convert(const float* __restrict__ w_fc) {
    int i = blockIdx.x * 256 + threadIdx.x;
    if (i < 392 * 224 / 4) {
        float4 v = *(const float4*)(w_fc + i * 4);
        __nv_bfloat16* d = g_wfc_bf + i * 4;
        d[0] = __float2bfloat16(v.x);
        d[1] = __float2bfloat16(v.y);
        d[2] = __float2bfloat16(v.z);
        d[3] = __float2bfloat16(v.w);
    }
}

// ---------------------------------------------------------------------------
// Kernel 2: HMMA bf16 GEMM: h = relu(latent @ w_fc^T + b_fc)
// ---------------------------------------------------------------------------
#define ASTR 232
#define K2_SMEM_BYTES ((128 * ASTR + 64 * ASTR) * 2)

__global__ void __launch_bounds__(256, 2) k2_gemm_mma(
    const float* __restrict__ b_fc)
{
    extern __shared__ __align__(16) __nv_bfloat16 sm[];
    __nv_bfloat16* sa = sm;               // [128][ASTR]
    __nv_bfloat16* sb = sm + 128 * ASTR;  // [64][ASTR]

    const int tid = threadIdx.x;
    const int wid = tid >> 5;
    const int lane = tid & 31;
    const int n0 = blockIdx.x * 64;
    const int m0 = blockIdx.y * 128;
    const int mw = (wid & 3) * 32;
    const int nw = (wid >> 2) * 32;

    for (int t = tid; t < 128 * 28; t += 256) {
        int r = t / 28, c = t - (t / 28) * 28;
        uint4 v = *(const uint4*)(g_latent_bf + (size_t)(m0 + r) * 224 + c * 8);
        *(uint4*)(sa + r * ASTR + c * 8) = v;
    }
    for (int t = tid; t < 64 * 28; t += 256) {
        int r = t / 28, c = t - (t / 28) * 28;
        int gn = n0 + r;
        uint4 v = make_uint4(0u, 0u, 0u, 0u);
        if (gn < 392) v = *(const uint4*)(g_wfc_bf + (size_t)gn * 224 + c * 8);
        *(uint4*)(sb + r * ASTR + c * 8) = v;
    }
    __syncthreads();

    float d[2][4][4];
#pragma unroll
    for (int mt = 0; mt < 2; mt++)
#pragma unroll
        for (int nt = 0; nt < 4; nt++)
#pragma unroll
            for (int e = 0; e < 4; e++) d[mt][nt][e] = 0.f;

    const uint32_t sa_base = smem_u32(sa);
    const uint32_t sb_base = smem_u32(sb);
    const int a_row = mw + (lane & 15);
    const int a_coff = (lane >> 4) * 8;
    const int b_row = nw + (lane & 7) + ((lane >> 4) & 1) * 8;
    const int b_coff = ((lane >> 3) & 1) * 8;

#pragma unroll
    for (int ks = 0; ks < 14; ks++) {
        const int k0 = ks * 16;
        uint32_t a0[4], a1[4];
        ldmatrix_x4(a0[0], a0[1], a0[2], a0[3],
                    sa_base + (uint32_t)((a_row) * ASTR + k0 + a_coff) * 2);
        ldmatrix_x4(a1[0], a1[1], a1[2], a1[3],
                    sa_base + (uint32_t)((a_row + 16) * ASTR + k0 + a_coff) * 2);
        uint32_t b01[4], b23[4];
        ldmatrix_x4(b01[0], b01[1], b01[2], b01[3],
                    sb_base + (uint32_t)((b_row) * ASTR + k0 + b_coff) * 2);
        ldmatrix_x4(b23[0], b23[1], b23[2], b23[3],
                    sb_base + (uint32_t)((b_row + 16) * ASTR + k0 + b_coff) * 2);
        mma_16816(d[0][0], a0, b01 + 0);
        mma_16816(d[0][1], a0, b01 + 2);
        mma_16816(d[0][2], a0, b23 + 0);
        mma_16816(d[0][3], a0, b23 + 2);
        mma_16816(d[1][0], a1, b01 + 0);
        mma_16816(d[1][1], a1, b01 + 2);
        mma_16816(d[1][2], a1, b23 + 0);
        mma_16816(d[1][3], a1, b23 + 2);
    }

    const int qrow = lane >> 2;
    const int qcol = (lane & 3) * 2;
#pragma unroll
    for (int nt = 0; nt < 4; nt++) {
        int gn = n0 + nw + nt * 8 + qcol;
        if (gn < 392) {
            float2 bv = *(const float2*)(b_fc + gn);
#pragma unroll
            for (int mt = 0; mt < 2; mt++) {
                int m = m0 + mw + mt * 16 + qrow;
                float2 o0, o1;
                o0.x = fmaxf(d[mt][nt][0] + bv.x, 0.f);
                o0.y = fmaxf(d[mt][nt][1] + bv.y, 0.f);
                o1.x = fmaxf(d[mt][nt][2] + bv.x, 0.f);
                o1.y = fmaxf(d[mt][nt][3] + bv.y, 0.f);
                *(float2*)(g_h + (size_t)m * 392 + gn) = o0;
                *(float2*)(g_h + (size_t)(m + 8) * 392 + gn) = o1;
            }
        }
    }
}

// ---------------------------------------------------------------------------
// Kernel 3: fused deconv1+relu+deconv2+sigmoid.
// One thread per (sample, i, j) of the 7x7 grid computes the FULL 4x4 output
// patch: 8 h loads feed all 16 y values (4x h-reuse vs item-per-parity).
// Block 256 threads = 5 samples (245 active). Weights: warp-uniform LDS.128.
// ---------------------------------------------------------------------------
__global__ void __launch_bounds__(256) k3_deconv(
    const float* __restrict__ w_d1, const float* __restrict__ b_d1,
    const float* __restrict__ w_d2, const float* __restrict__ b_d2,
    float* __restrict__ out)
{
    __shared__ float shh[5 * 392];
    __shared__ float sw1r[128];    // [c][p][o]: sw1r[(c*4+p)*4+o] = w_d1[c*16+o*4+p]
    __shared__ float sw2r[16];     // [dk][o]:   sw2r[dk*4+o]      = w_d2[o*4+dk]
    __shared__ float sb1v[4];
    __shared__ float sb2s;

    const int tid = threadIdx.x;
    const int b0 = blockIdx.x * 5;
    const int nsamp = (BATCH - b0 < 5) ? (BATCH - b0) : 5;

    if (tid < 128) {
        int c = tid >> 4, p = (tid >> 2) & 3, o = tid & 3;
        sw1r[tid] = w_d1[c * 16 + o * 4 + p];
    } else if (tid < 144) {
        int t = tid - 128;
        sw2r[t] = w_d2[(t & 3) * 4 + (t >> 2)];
    } else if (tid < 148) sb1v[tid - 144] = b_d1[tid - 144];
    else if (tid == 148) sb2s = b_d2[0];

    // stage h for nsamp samples: contiguous, coalesced float4
    {
        const float4* src = (const float4*)(g_h + (size_t)b0 * 392);
        float4* dst = (float4*)shh;
        const int nf4 = nsamp * 98;
        for (int t = tid; t < nf4; t += 256) dst[t] = src[t];
    }
    __syncthreads();

    const int s = tid / 49;
    const int q = tid - s * 49;
    if (s < nsamp) {
        const int i = q / 7;
        const int j = q - i * 7;
        const float* hp = shh + s * 392 + q;

        // y as yv[p][o], p = d1*2+k1
        float4 yv[4];
#pragma unroll
        for (int p = 0; p < 4; p++)
            yv[p] = make_float4(sb1v[0], sb1v[1], sb1v[2], sb1v[3]);
#pragma unroll
        for (int c = 0; c < 8; c++) {
            float hv = hp[c * 49];
#pragma unroll
            for (int p = 0; p < 4; p++) {
                float4 wv = *(const float4*)(sw1r + (c * 4 + p) * 4);
                yv[p].x = fmaf(hv, wv.x, yv[p].x);
                yv[p].y = fmaf(hv, wv.y, yv[p].y);
                yv[p].z = fmaf(hv, wv.z, yv[p].z);
                yv[p].w = fmaf(hv, wv.w, yv[p].w);
            }
        }
#pragma unroll
        for (int p = 0; p < 4; p++) {
            yv[p].x = fmaxf(yv[p].x, 0.f);
            yv[p].y = fmaxf(yv[p].y, 0.f);
            yv[p].z = fmaxf(yv[p].z, 0.f);
            yv[p].w = fmaxf(yv[p].w, 0.f);
        }

        float* ob = out + (size_t)(b0 + s) * 784 + (4 * i) * 28 + 4 * j;
#pragma unroll
        for (int rr = 0; rr < 4; rr++) {
            const int d1 = rr >> 1, d2 = rr & 1;
            float4 w2a = *(const float4*)(sw2r + (d2 * 2 + 0) * 4);  // k2=0
            float4 w2b = *(const float4*)(sw2r + (d2 * 2 + 1) * 4);  // k2=1
            float4 v;
            {
                float4 yp = yv[d1 * 2 + 0];  // k1=0
                float a0 = sb2s, a1 = sb2s;
                a0 = fmaf(yp.x, w2a.x, a0); a0 = fmaf(yp.y, w2a.y, a0);
                a0 = fmaf(yp.z, w2a.z, a0); a0 = fmaf(yp.w, w2a.w, a0);
                a1 = fmaf(yp.x, w2b.x, a1); a1 = fmaf(yp.y, w2b.y, a1);
                a1 = fmaf(yp.z, w2b.z, a1); a1 = fmaf(yp.w, w2b.w, a1);
                v.x = __fdividef(1.0f, 1.0f + __expf(-a0));
                v.y = __fdividef(1.0f, 1.0f + __expf(-a1));
            }
            {
                float4 yp = yv[d1 * 2 + 1];  // k1=1
                float a0 = sb2s, a1 = sb2s;
                a0 = fmaf(yp.x, w2a.x, a0); a0 = fmaf(yp.y, w2a.y, a0);
                a0 = fmaf(yp.z, w2a.z, a0); a0 = fmaf(yp.w, w2a.w, a0);
                a1 = fmaf(yp.x, w2b.x, a1); a1 = fmaf(yp.y, w2b.y, a1);
                a1 = fmaf(yp.z, w2b.z, a1); a1 = fmaf(yp.w, w2b.w, a1);
                v.z = __fdividef(1.0f, 1.0f + __expf(-a0));
                v.w = __fdividef(1.0f, 1.0f + __expf(-a1));
            }
            *(float4*)(ob + (2 * d1 + d2) * 28) = v;
        }
    }
}

// ---------------------------------------------------------------------------
// Launch
// ---------------------------------------------------------------------------
extern "C" void kernel_launch(void* const* d_in, const int* in_sizes, int n_in,
                              void* d_out, int out_size)
{
    const float* x          = (const float*)d_in[0];
    const float* var_params = (const float*)d_in[1];
    const float* w_lat      = (const float*)d_in[2];
    const float* b_lat      = (const float*)d_in[3];
    const float* w_fc       = (const float*)d_in[4];
    const float* b_fc       = (const float*)d_in[5];
    const float* w_d1       = (const float*)d_in[6];
    const float* b_d1       = (const float*)d_in[7];
    const float* w_d2       = (const float*)d_in[8];
    const float* b_d2       = (const float*)d_in[9];
    float* out = (float*)d_out;

    cudaFuncSetAttribute(k2_gemm_mma, cudaFuncAttributeMaxDynamicSharedMemorySize,
                         K2_SMEM_BYTES);

    k1_quad_latent<<<BATCH / 32, 256>>>(x, var_params, w_lat, b_lat);
    k2a_convert<<<(392 * 224 / 4 + 255) / 256, 256>>>(w_fc);
    k2_gemm_mma<<<dim3(7, BATCH / 128), 256, K2_SMEM_BYTES>>>(b_fc);
    k3_deconv<<<(BATCH + 4) / 5, 256>>>(w_d1, b_d1, w_d2, b_d2, out);
}